// round 11
// baseline (speedup 1.0000x reference)
#include <cuda_runtime.h>
#include <stdint.h>

// Problem constants
#define NPTS   512          // number of nodes (rows of x)
#define NIN    256          // input feature dim
#define NOUT   256          // output feature dim
#define NCOMB  512          // combined projection width: [A' | B]

// Scratch for the pre-projection O[i][o'] : o'<256 -> A'[i][o'] (bias folded),
// o'>=256 -> B[i][o'-256].  512*512 floats = 1 MB.
__device__ float g_O[NPTS * NCOMB];

// ---------------------------------------------------------------------------
// Kernel 1: O = X @ V, V[k][o'] = W[o'][k] (o'<256) or W[o'-256][256+k] (o'>=256)
// Bias added to the A' half. Tiled SGEMM: 64x64 C-tile, 16-wide K panels,
// blockDim (16,16), each thread a 4x4 micro-tile with stride-16 mapping
// (conflict-free shared loads).
// ---------------------------------------------------------------------------
__global__ __launch_bounds__(256) void proj_gemm_kernel(
    const float* __restrict__ X,   // [512, 256]
    const float* __restrict__ W,   // [256, 512]
    const float* __restrict__ bias // [256]
) {
    __shared__ float Xs[16][64];   // [kk][row]
    __shared__ float Vs[16][64];   // [kk][col]

    const int tx  = threadIdx.x;          // 0..15
    const int ty  = threadIdx.y;          // 0..15
    const int tid = ty * 16 + tx;         // 0..255
    const int r0  = blockIdx.y * 64;      // row tile origin
    const int o0  = blockIdx.x * 64;      // col tile origin

    float acc[4][4];
#pragma unroll
    for (int q = 0; q < 4; q++)
#pragma unroll
        for (int p = 0; p < 4; p++) acc[q][p] = 0.0f;

    for (int kt = 0; kt < NIN; kt += 16) {
        // Load X panel: 64 rows x 16 k. idx -> (r = idx>>4, kk = idx&15)
#pragma unroll
        for (int rep = 0; rep < 4; rep++) {
            int idx = tid + rep * 256;
            int r   = idx >> 4;
            int kk  = idx & 15;
            Xs[kk][r] = X[(r0 + r) * NIN + kt + kk];
        }
        // Load V panel: 16 k x 64 cols. idx -> (kk = idx>>6, oo = idx&63)
#pragma unroll
        for (int rep = 0; rep < 4; rep++) {
            int idx = tid + rep * 256;
            int kk  = idx >> 6;
            int oo  = idx & 63;
            int o   = o0 + oo;
            int k   = kt + kk;
            float v = (o < NOUT) ? W[o * (2 * NIN) + k]
                                 : W[(o - NOUT) * (2 * NIN) + NIN + k];
            Vs[kk][oo] = v;
        }
        __syncthreads();

#pragma unroll
        for (int kk = 0; kk < 16; kk++) {
            float xr[4], vo[4];
#pragma unroll
            for (int q = 0; q < 4; q++) xr[q] = Xs[kk][ty + 16 * q];
#pragma unroll
            for (int p = 0; p < 4; p++) vo[p] = Vs[kk][tx + 16 * p];
#pragma unroll
            for (int q = 0; q < 4; q++)
#pragma unroll
                for (int p = 0; p < 4; p++) acc[q][p] += xr[q] * vo[p];
        }
        __syncthreads();
    }

    // Store, folding bias into the A' half (o < 256).
#pragma unroll
    for (int q = 0; q < 4; q++) {
        int r = r0 + ty + 16 * q;
#pragma unroll
        for (int p = 0; p < 4; p++) {
            int o   = o0 + tx + 16 * p;
            float v = acc[q][p] + ((o < NOUT) ? bias[o] : 0.0f);
            g_O[r * NCOMB + o] = v;
        }
    }
}

// ---------------------------------------------------------------------------
// Kernel 2: fill out[i][j][c] = A'[min(i,j)][c] + B[max(i,j)][c], 0 on diag.
// Grid (64, 64) of 8x8 (i,j) tiles; only upper-triangular tiles (ti<=tj) work.
// 256 threads, one channel c per thread. A'/B rows for the tile are held in
// registers (8+8 floats), then 64 pair values computed and written to BOTH
// (i,j) and (j,i) rows — each row is 1KB contiguous, fully coalesced.
// Store-bound: 268 MB total stores, ~35 MB L2 reads.
// ---------------------------------------------------------------------------
#define TI 8
#define TJ 8

__global__ __launch_bounds__(256) void pairwise_fill_kernel(float* __restrict__ out) {
    const int ti = blockIdx.y;
    const int tj = blockIdx.x;
    if (tj < ti) return;   // lower-triangular tiles handled via symmetric writes

    const int c = threadIdx.x;   // channel 0..255
    const float* __restrict__ O = g_O;

    // A'[ti*8+ii][c] and B[tj*8+jj][c]
    float a[TI], b[TJ];
#pragma unroll
    for (int ii = 0; ii < TI; ii++)
        a[ii] = O[(ti * TI + ii) * NCOMB + c];
#pragma unroll
    for (int jj = 0; jj < TJ; jj++)
        b[jj] = O[(tj * TJ + jj) * NCOMB + NOUT + c];

    if (ti != tj) {
        // All pairs satisfy i < j.
#pragma unroll
        for (int ii = 0; ii < TI; ii++) {
            const int i = ti * TI + ii;
#pragma unroll
            for (int jj = 0; jj < TJ; jj++) {
                const int j = tj * TJ + jj;
                const float v = a[ii] + b[jj];
                out[((uint32_t)i * NPTS + j) * NOUT + c] = v;  // (i,j)
                out[((uint32_t)j * NPTS + i) * NOUT + c] = v;  // (j,i) symmetric
            }
        }
    } else {
        // Diagonal tile: i<j pairs write both sides; i==j writes zero.
#pragma unroll
        for (int ii = 0; ii < TI; ii++) {
            const int i = ti * TI + ii;
#pragma unroll
            for (int jj = 0; jj < TJ; jj++) {
                const int j = tj * TJ + jj;
                if (ii < jj) {
                    const float v = a[ii] + b[jj];
                    out[((uint32_t)i * NPTS + j) * NOUT + c] = v;
                    out[((uint32_t)j * NPTS + i) * NOUT + c] = v;
                } else if (ii == jj) {
                    out[((uint32_t)i * NPTS + j) * NOUT + c] = 0.0f;
                }
            }
        }
    }
}

// ---------------------------------------------------------------------------
// Launch
// ---------------------------------------------------------------------------
extern "C" void kernel_launch(void* const* d_in, const int* in_sizes, int n_in,
                              void* d_out, int out_size) {
    const float* x = (const float*)d_in[0];   // [512, 256]
    const float* W = (const float*)d_in[1];   // [256, 512]
    const float* b = (const float*)d_in[2];   // [256]
    float* out = (float*)d_out;               // [512, 512, 256]

    (void)in_sizes; (void)n_in; (void)out_size;

    // 1) Pre-projection: O = [X@W1^T + b | X@W2^T]
    {
        dim3 grid(NCOMB / 64, NPTS / 64);   // (8, 8)
        dim3 block(16, 16);
        proj_gemm_kernel<<<grid, block>>>(x, W, b);
    }
    // 2) Broadcast-add fill of the symmetric pairwise output.
    {
        dim3 grid(NPTS / TJ, NPTS / TI);    // (64, 64), upper-tri active
        pairwise_fill_kernel<<<grid, 256>>>(out);
    }
}

// round 12
// speedup vs baseline: 1.5054x; 1.5054x over previous
#include <cuda_runtime.h>
#include <stdint.h>

// Problem constants
#define NPTS   512          // number of nodes (rows of x)
#define NIN    256          // input feature dim
#define NOUT   256          // output feature dim
#define NCOMB  512          // combined projection width: [A' | B]

// Scratch: O[i][o'] ; o'<256 -> A'[i][o'] (bias folded), o'>=256 -> B[i][o'-256].
__device__ float g_O[NPTS * NCOMB];   // 1 MB

// ---------------------------------------------------------------------------
// Kernel 1: O = X @ V,  V[k][o'] = W[o'][k] (o'<256) or W[o'-256][256+k].
// Tile 64 rows x 32 cols -> grid (16,8) = 128 CTAs (~1 per SM).
// K panels of 32, float4 global loads, padded SMEM (conflict-free transpose),
// micro-tile 4 rows x 2 cols per thread (LDS.128 broadcast + LDS.64).
// ---------------------------------------------------------------------------
#define GK 32                 // K panel
#define XPAD 68               // 64 rows + pad, 16B-aligned row pitch (68*4=272)
#define VPAD 34               // 32 cols + pad, 8B-aligned row pitch

__global__ __launch_bounds__(256) void proj_gemm_kernel(
    const float* __restrict__ X,   // [512, 256]
    const float* __restrict__ W,   // [256, 512]
    const float* __restrict__ bias // [256]
) {
    __shared__ float Xs[GK][XPAD]; // [kk][row]
    __shared__ float Vs[GK][VPAD]; // [kk][col]

    const int tx  = threadIdx.x;           // 0..15 -> col pair 2*tx
    const int ty  = threadIdx.y;           // 0..15 -> row quad 4*ty
    const int tid = ty * 16 + tx;
    const int o0  = blockIdx.x * 32;       // col tile origin (combined width)
    const int r0  = blockIdx.y * 64;       // row tile origin

    float acc[4][2];
#pragma unroll
    for (int q = 0; q < 4; q++) { acc[q][0] = 0.0f; acc[q][1] = 0.0f; }

    for (int kt = 0; kt < NIN; kt += GK) {
        // --- X panel: 64 rows x 32 k = 2048 floats = 2 float4 per thread ---
#pragma unroll
        for (int rep = 0; rep < 2; rep++) {
            int lin = tid + rep * 256;          // 0..511
            int r   = lin >> 3;                 // 0..63
            int kkg = (lin & 7) << 2;           // 0,4,..,28
            float4 v = *(const float4*)&X[(r0 + r) * NIN + kt + kkg];
            Xs[kkg + 0][r] = v.x;
            Xs[kkg + 1][r] = v.y;
            Xs[kkg + 2][r] = v.z;
            Xs[kkg + 3][r] = v.w;
        }
        // --- V panel: 32 cols x 32 k = 1024 floats = 1 float4 per thread ---
        {
            int oo  = tid >> 3;                 // 0..31
            int kkg = (tid & 7) << 2;
            int o   = o0 + oo;
            const float* wrow = (o < NOUT)
                ? &W[o * (2 * NIN) + kt + kkg]
                : &W[(o - NOUT) * (2 * NIN) + NIN + kt + kkg];
            float4 v = *(const float4*)wrow;
            Vs[kkg + 0][oo] = v.x;
            Vs[kkg + 1][oo] = v.y;
            Vs[kkg + 2][oo] = v.z;
            Vs[kkg + 3][oo] = v.w;
        }
        __syncthreads();

#pragma unroll
        for (int kk = 0; kk < GK; kk++) {
            float4 xr = *(const float4*)&Xs[kk][4 * ty];  // broadcast across tx
            float2 vo = *(const float2*)&Vs[kk][2 * tx];
            acc[0][0] += xr.x * vo.x;  acc[0][1] += xr.x * vo.y;
            acc[1][0] += xr.y * vo.x;  acc[1][1] += xr.y * vo.y;
            acc[2][0] += xr.z * vo.x;  acc[2][1] += xr.z * vo.y;
            acc[3][0] += xr.w * vo.x;  acc[3][1] += xr.w * vo.y;
        }
        __syncthreads();
    }

    // Store, folding bias into the A' half (o < 256).
    const int oA = o0 + 2 * tx;
    const int oB = oA + 1;
    const float biasA = (oA < NOUT) ? bias[oA] : 0.0f;
    const float biasB = (oB < NOUT) ? bias[oB] : 0.0f;
#pragma unroll
    for (int q = 0; q < 4; q++) {
        int r = r0 + 4 * ty + q;
        g_O[r * NCOMB + oA] = acc[q][0] + biasA;
        g_O[r * NCOMB + oB] = acc[q][1] + biasB;
    }
}

// ---------------------------------------------------------------------------
// Kernel 2: out[i][j][:] = A'[min(i,j)] + B[max(i,j)], 0 on diagonal.
// Grid (64,64) of 8x8 (i,j) tiles; only upper-triangular tiles work.
// 256 threads: c4 = tid&63 (float4 channel group), rsel = tid>>6 picks
// ii in {2*rsel, 2*rsel+1}. float4 math + streaming STG.128 (__stcs):
// each (u,jj) pair writes 512B contiguous per warp, both (i,j) and (j,i).
// ---------------------------------------------------------------------------
__global__ __launch_bounds__(256) void pairwise_fill_kernel(float4* __restrict__ out) {
    const int ti = blockIdx.y;
    const int tj = blockIdx.x;
    if (tj < ti) return;

    const int c4   = threadIdx.x & 63;      // 0..63 : channel/4
    const int rsel = threadIdx.x >> 6;      // 0..3
    const float4* __restrict__ O4 = (const float4*)g_O;  // rows of 128 float4

    // A'[ti*8 + 2*rsel + u][c] and B[tj*8 + jj][c]
    float4 a[2], b[8];
#pragma unroll
    for (int u = 0; u < 2; u++)
        a[u] = O4[(uint32_t)(ti * 8 + 2 * rsel + u) * 128 + c4];
#pragma unroll
    for (int jj = 0; jj < 8; jj++)
        b[jj] = O4[(uint32_t)(tj * 8 + jj) * 128 + 64 + c4];

    if (ti != tj) {
#pragma unroll
        for (int u = 0; u < 2; u++) {
            const int i = ti * 8 + 2 * rsel + u;
#pragma unroll
            for (int jj = 0; jj < 8; jj++) {
                const int j = tj * 8 + jj;
                float4 v;
                v.x = a[u].x + b[jj].x;
                v.y = a[u].y + b[jj].y;
                v.z = a[u].z + b[jj].z;
                v.w = a[u].w + b[jj].w;
                __stcs(&out[((uint32_t)i * NPTS + j) * 64 + c4], v);
                __stcs(&out[((uint32_t)j * NPTS + i) * 64 + c4], v);
            }
        }
    } else {
        // Diagonal tile: local row index li = 2*rsel+u vs local col jj.
#pragma unroll
        for (int u = 0; u < 2; u++) {
            const int li = 2 * rsel + u;
            const int i  = ti * 8 + li;
#pragma unroll
            for (int jj = 0; jj < 8; jj++) {
                const int j = tj * 8 + jj;
                if (li < jj) {
                    float4 v;
                    v.x = a[u].x + b[jj].x;
                    v.y = a[u].y + b[jj].y;
                    v.z = a[u].z + b[jj].z;
                    v.w = a[u].w + b[jj].w;
                    __stcs(&out[((uint32_t)i * NPTS + j) * 64 + c4], v);
                    __stcs(&out[((uint32_t)j * NPTS + i) * 64 + c4], v);
                } else if (li == jj) {
                    float4 z = make_float4(0.f, 0.f, 0.f, 0.f);
                    __stcs(&out[((uint32_t)i * NPTS + j) * 64 + c4], z);
                }
            }
        }
    }
}

// ---------------------------------------------------------------------------
// Launch
// ---------------------------------------------------------------------------
extern "C" void kernel_launch(void* const* d_in, const int* in_sizes, int n_in,
                              void* d_out, int out_size) {
    const float* x = (const float*)d_in[0];   // [512, 256]
    const float* W = (const float*)d_in[1];   // [256, 512]
    const float* b = (const float*)d_in[2];   // [256]
    float4* out = (float4*)d_out;             // [512, 512, 256] fp32

    (void)in_sizes; (void)n_in; (void)out_size;

    // 1) Pre-projection: O = [X@W1^T + b | X@W2^T], 128 CTAs.
    {
        dim3 grid(NCOMB / 32, NPTS / 64);   // (16, 8)
        dim3 block(16, 16);
        proj_gemm_kernel<<<grid, block>>>(x, W, b);
    }
    // 2) Broadcast-add fill of the symmetric pairwise output.
    {
        dim3 grid(NPTS / 8, NPTS / 8);      // (64, 64), upper-tri active
        pairwise_fill_kernel<<<grid, 256>>>(out);
    }
}

// round 13
// speedup vs baseline: 1.6298x; 1.0826x over previous
#include <cuda_runtime.h>
#include <stdint.h>

// Problem constants
#define NPTS   512          // number of nodes (rows of x)
#define NIN    256          // input feature dim
#define NOUT   256          // output feature dim
#define NCOMB  512          // combined projection width: [A' | B]

// Scratch: O[i][o'] ; o'<256 -> A'[i][o'] (bias folded), o'>=256 -> B[i][o'-256].
__device__ float g_O[NPTS * NCOMB];   // 1 MB (stays L2-resident for the fill)

// ---------------------------------------------------------------------------
// Kernel 1: O = X @ V,  V[k][o'] = W[o'][k] (o'<256) or W[o'-256][256+k].
// Tile 64 rows x 32 cols -> grid (16,8) = 128 CTAs. K panels of 32 with a
// DOUBLE-BUFFERED smem pipeline: global loads for panel p+1 are issued into
// registers before the compute over panel p, one __syncthreads per panel.
// Micro-tile 4x2 per thread: LDS.128 broadcast + LDS.64.
// ---------------------------------------------------------------------------
#define GK    32
#define NPAN  (NIN / GK)      // 8 panels
#define XPAD  68              // 64 rows + pad (16B-aligned pitch)
#define VPAD  34              // 32 cols + pad (8B-aligned pitch)

__global__ __launch_bounds__(256) void proj_gemm_kernel(
    const float* __restrict__ X,   // [512, 256]
    const float* __restrict__ W,   // [256, 512]
    const float* __restrict__ bias // [256]
) {
    __shared__ float Xs[2][GK][XPAD];
    __shared__ float Vs[2][GK][VPAD];

    const int tx  = threadIdx.x;           // 0..15 -> col pair 2*tx
    const int ty  = threadIdx.y;           // 0..15 -> row quad 4*ty
    const int tid = ty * 16 + tx;
    const int o0  = blockIdx.x * 32;       // col tile origin (combined width)
    const int r0  = blockIdx.y * 64;       // row tile origin

    // Global source pointers for this thread's panel loads (advance by GK each panel)
    const int xr0 = tid >> 3;               // 0..31  (row for rep 0)
    const int xkk = (tid & 7) << 2;         // 0,4,..,28
    const float* xsrc0 = &X[(r0 + xr0)      * NIN + xkk];
    const float* xsrc1 = &X[(r0 + xr0 + 32) * NIN + xkk];
    const int voo = tid >> 3;               // 0..31
    const int o   = o0 + voo;
    const float* vsrc = (o < NOUT) ? &W[o * (2 * NIN) + xkk]
                                   : &W[(o - NOUT) * (2 * NIN) + NIN + xkk];

    float acc[4][2];
#pragma unroll
    for (int q = 0; q < 4; q++) { acc[q][0] = 0.0f; acc[q][1] = 0.0f; }

    // Preload panel 0 into buffer 0
    {
        float4 x0 = *(const float4*)xsrc0;
        float4 x1 = *(const float4*)xsrc1;
        float4 v  = *(const float4*)vsrc;
        Xs[0][xkk+0][xr0]    = x0.x; Xs[0][xkk+1][xr0]    = x0.y;
        Xs[0][xkk+2][xr0]    = x0.z; Xs[0][xkk+3][xr0]    = x0.w;
        Xs[0][xkk+0][xr0+32] = x1.x; Xs[0][xkk+1][xr0+32] = x1.y;
        Xs[0][xkk+2][xr0+32] = x1.z; Xs[0][xkk+3][xr0+32] = x1.w;
        Vs[0][xkk+0][voo] = v.x; Vs[0][xkk+1][voo] = v.y;
        Vs[0][xkk+2][voo] = v.z; Vs[0][xkk+3][voo] = v.w;
    }
    __syncthreads();

#pragma unroll
    for (int p = 0; p < NPAN; p++) {
        const int buf = p & 1;
        float4 nx0, nx1, nv;
        if (p + 1 < NPAN) {
            nx0 = *(const float4*)(xsrc0 + (p + 1) * GK);
            nx1 = *(const float4*)(xsrc1 + (p + 1) * GK);
            nv  = *(const float4*)(vsrc  + (p + 1) * GK);
        }
#pragma unroll
        for (int kk = 0; kk < GK; kk++) {
            float4 xr = *(const float4*)&Xs[buf][kk][4 * ty];
            float2 vo = *(const float2*)&Vs[buf][kk][2 * tx];
            acc[0][0] += xr.x * vo.x;  acc[0][1] += xr.x * vo.y;
            acc[1][0] += xr.y * vo.x;  acc[1][1] += xr.y * vo.y;
            acc[2][0] += xr.z * vo.x;  acc[2][1] += xr.z * vo.y;
            acc[3][0] += xr.w * vo.x;  acc[3][1] += xr.w * vo.y;
        }
        if (p + 1 < NPAN) {
            const int nb = buf ^ 1;
            Xs[nb][xkk+0][xr0]    = nx0.x; Xs[nb][xkk+1][xr0]    = nx0.y;
            Xs[nb][xkk+2][xr0]    = nx0.z; Xs[nb][xkk+3][xr0]    = nx0.w;
            Xs[nb][xkk+0][xr0+32] = nx1.x; Xs[nb][xkk+1][xr0+32] = nx1.y;
            Xs[nb][xkk+2][xr0+32] = nx1.z; Xs[nb][xkk+3][xr0+32] = nx1.w;
            Vs[nb][xkk+0][voo] = nv.x; Vs[nb][xkk+1][voo] = nv.y;
            Vs[nb][xkk+2][voo] = nv.z; Vs[nb][xkk+3][voo] = nv.w;
        }
        __syncthreads();
    }

    // Store, folding bias into the A' half (o < 256).
    const int oA = o0 + 2 * tx;
    const int oB = oA + 1;
    const float biasA = (oA < NOUT) ? bias[oA] : 0.0f;
    const float biasB = (oB < NOUT) ? bias[oB] : 0.0f;
#pragma unroll
    for (int q = 0; q < 4; q++) {
        int r = r0 + 4 * ty + q;
        g_O[r * NCOMB + oA] = acc[q][0] + biasA;
        g_O[r * NCOMB + oB] = acc[q][1] + biasB;
    }
}

// ---------------------------------------------------------------------------
// Kernel 2: out[i][j][:] = A'[min(i,j)] + B[max(i,j)], 0 on diagonal.
// ALL 4096 tiles active; each CTA writes ONLY its own 8x8 tile -> perfectly
// uniform work, stores form contiguous 8KB runs per output row. O table
// (1 MB) is L2-resident, so the extra reads cost ~no DRAM traffic.
// 256 threads: c4 = tid&63 (float4 channel), rsel = tid>>6 -> 2 i-rows each.
// ---------------------------------------------------------------------------
__global__ __launch_bounds__(256) void pairwise_fill_kernel(float4* __restrict__ out) {
    const int ti = blockIdx.y;
    const int tj = blockIdx.x;

    const int c4   = threadIdx.x & 63;      // 0..63 : channel/4
    const int rsel = threadIdx.x >> 6;      // 0..3
    const float4* __restrict__ O4 = (const float4*)g_O;  // rows of 128 float4

    if (ti < tj) {
        // i < j everywhere: val = A'[i] + B[j]
        float4 a[2], b[8];
#pragma unroll
        for (int u = 0; u < 2; u++)
            a[u] = O4[(uint32_t)(ti * 8 + 2 * rsel + u) * 128 + c4];
#pragma unroll
        for (int jj = 0; jj < 8; jj++)
            b[jj] = O4[(uint32_t)(tj * 8 + jj) * 128 + 64 + c4];
#pragma unroll
        for (int u = 0; u < 2; u++) {
            const int i = ti * 8 + 2 * rsel + u;
#pragma unroll
            for (int jj = 0; jj < 8; jj++) {
                const int j = tj * 8 + jj;
                float4 v;
                v.x = a[u].x + b[jj].x;
                v.y = a[u].y + b[jj].y;
                v.z = a[u].z + b[jj].z;
                v.w = a[u].w + b[jj].w;
                __stcs(&out[((uint32_t)i * NPTS + j) * 64 + c4], v);
            }
        }
    } else if (ti > tj) {
        // j < i everywhere: val = A'[j] + B[i]
        float4 a[8], b[2];
#pragma unroll
        for (int jj = 0; jj < 8; jj++)
            a[jj] = O4[(uint32_t)(tj * 8 + jj) * 128 + c4];
#pragma unroll
        for (int u = 0; u < 2; u++)
            b[u] = O4[(uint32_t)(ti * 8 + 2 * rsel + u) * 128 + 64 + c4];
#pragma unroll
        for (int u = 0; u < 2; u++) {
            const int i = ti * 8 + 2 * rsel + u;
#pragma unroll
            for (int jj = 0; jj < 8; jj++) {
                const int j = tj * 8 + jj;
                float4 v;
                v.x = a[jj].x + b[u].x;
                v.y = a[jj].y + b[u].y;
                v.z = a[jj].z + b[u].z;
                v.w = a[jj].w + b[u].w;
                __stcs(&out[((uint32_t)i * NPTS + j) * 64 + c4], v);
            }
        }
    } else {
        // Diagonal tile (64 CTAs, cold path): direct L2 reads, low unroll to
        // keep register pressure off the hot paths.
        const int base = ti * 8;
#pragma unroll 1
        for (int u = 0; u < 2; u++) {
            const int li = 2 * rsel + u;
            const int i  = base + li;
#pragma unroll 1
            for (int jj = 0; jj < 8; jj++) {
                const int j = base + jj;
                float4 v;
                if (li == jj) {
                    v = make_float4(0.f, 0.f, 0.f, 0.f);
                } else {
                    const int mn = li < jj ? li : jj;
                    const int mx = li < jj ? jj : li;
                    float4 va = O4[(uint32_t)(base + mn) * 128 + c4];
                    float4 vb = O4[(uint32_t)(base + mx) * 128 + 64 + c4];
                    v.x = va.x + vb.x; v.y = va.y + vb.y;
                    v.z = va.z + vb.z; v.w = va.w + vb.w;
                }
                __stcs(&out[((uint32_t)i * NPTS + j) * 64 + c4], v);
            }
        }
    }
}

// ---------------------------------------------------------------------------
// Launch
// ---------------------------------------------------------------------------
extern "C" void kernel_launch(void* const* d_in, const int* in_sizes, int n_in,
                              void* d_out, int out_size) {
    const float* x = (const float*)d_in[0];   // [512, 256]
    const float* W = (const float*)d_in[1];   // [256, 512]
    const float* b = (const float*)d_in[2];   // [256]
    float4* out = (float4*)d_out;             // [512, 512, 256] fp32

    (void)in_sizes; (void)n_in; (void)out_size;

    // 1) Pre-projection: O = [X@W1^T + b | X@W2^T], 128 CTAs, double-buffered.
    {
        dim3 grid(NCOMB / 32, NPTS / 64);   // (16, 8)
        dim3 block(16, 16);
        proj_gemm_kernel<<<grid, block>>>(x, W, b);
    }
    // 2) Broadcast-add fill: all tiles active, each writes only its own tile.
    {
        dim3 grid(NPTS / 8, NPTS / 8);      // (64, 64)
        pairwise_fill_kernel<<<grid, 256>>>(out);
    }
}